// round 14
// baseline (speedup 1.0000x reference)
#include <cuda_runtime.h>
#include <cuda_fp16.h>
#include <math.h>
#include <stdint.h>

// Problem constants
#define BB 4
#define SS 4096
#define EE 1024
#define HH 1024
#define NTOK (BB * SS)            // 16384
#define QKV_LD (3 * HH)           // 3072

// Scratch (device globals)
__device__ __half g_qkvh[(size_t)NTOK * QKV_LD];   // GEMM1 out / attn in (fp16)
__device__ __half g_attnh[(size_t)NTOK * HH];      // attn out / GEMM3 A (fp16)
__device__ __half g_xh[(size_t)NTOK * EE];         // x fp16
__device__ __half g_wqkvt[(size_t)QKV_LD * EE];    // W_qkv^T fp16 [3072][1024]
__device__ __half g_wouth[(size_t)HH * HH];        // W_out fp16 [1024][1024] ([n][k])

// ---------------------------------------------------------------------------
// helpers
// ---------------------------------------------------------------------------
__device__ __forceinline__ uint32_t smem_u32(const void* p) {
    return (uint32_t)__cvta_generic_to_shared(p);
}
__device__ __forceinline__ void cp16(uint32_t dst, const void* g) {
    asm volatile("cp.async.cg.shared.global [%0], [%1], 16;\n" :: "r"(dst), "l"(g));
}
__device__ __forceinline__ void cp_commit() {
    asm volatile("cp.async.commit_group;\n");
}
template <int N> __device__ __forceinline__ void cp_wait() {
    asm volatile("cp.async.wait_group %0;\n" :: "n"(N));
}

// fp16 mma, fp32 accumulate: D = A(16x16) * B(16x8) + D
__device__ __forceinline__ void mma_f16(float c[4], const uint32_t a[4],
                                        const uint32_t b[2]) {
    asm volatile(
        "mma.sync.aligned.m16n8k16.row.col.f32.f16.f16.f32 "
        "{%0,%1,%2,%3}, {%4,%5,%6,%7}, {%8,%9}, {%0,%1,%2,%3};\n"
        : "+f"(c[0]), "+f"(c[1]), "+f"(c[2]), "+f"(c[3])
        : "r"(a[0]), "r"(a[1]), "r"(a[2]), "r"(a[3]), "r"(b[0]), "r"(b[1]));
}

__device__ __forceinline__ void ldsm_x4(uint32_t& r0, uint32_t& r1,
                                        uint32_t& r2, uint32_t& r3, uint32_t a) {
    asm volatile("ldmatrix.sync.aligned.m8n8.x4.shared.b16 {%0,%1,%2,%3}, [%4];"
                 : "=r"(r0), "=r"(r1), "=r"(r2), "=r"(r3) : "r"(a));
}
__device__ __forceinline__ void ldsm_x4_t(uint32_t& r0, uint32_t& r1,
                                          uint32_t& r2, uint32_t& r3, uint32_t a) {
    asm volatile("ldmatrix.sync.aligned.m8n8.x4.trans.shared.b16 {%0,%1,%2,%3}, [%4];"
                 : "=r"(r0), "=r"(r1), "=r"(r2), "=r"(r3) : "r"(a));
}

// XOR swizzle, 128B rows (8 x 16B chunks): chunk c of row r at c^(r&7)
__device__ __forceinline__ uint32_t swz128(int r, int c) {
    return (uint32_t)(r * 128 + ((c ^ (r & 7)) << 4));
}
// XOR swizzle, 256B rows (16 x 16B chunks)
__device__ __forceinline__ uint32_t swz256(int r, int c) {
    return (uint32_t)(r * 256 + ((c ^ (r & 7)) << 4));
}

// ---------------------------------------------------------------------------
// conversions
// ---------------------------------------------------------------------------
__global__ void cvt_half_kernel(const float* __restrict__ in,
                                __half* __restrict__ out, int n4) {
    int i = blockIdx.x * blockDim.x + threadIdx.x;
    int stride = gridDim.x * blockDim.x;
    for (; i < n4; i += stride) {
        float4 v = reinterpret_cast<const float4*>(in)[i];
        reinterpret_cast<__half2*>(out)[i * 2 + 0] = __floats2half2_rn(v.x, v.y);
        reinterpret_cast<__half2*>(out)[i * 2 + 1] = __floats2half2_rn(v.z, v.w);
    }
}

__global__ void transpose_cvt_kernel(const float* __restrict__ in,
                                     __half* __restrict__ out, int R, int C) {
    __shared__ float t[32][33];
    int bx = blockIdx.x * 32;   // C
    int by = blockIdx.y * 32;   // R
#pragma unroll
    for (int i = threadIdx.y; i < 32; i += 8)
        t[i][threadIdx.x] = in[(size_t)(by + i) * C + bx + threadIdx.x];
    __syncthreads();
#pragma unroll
    for (int i = threadIdx.y; i < 32; i += 8)
        out[(size_t)(bx + i) * R + by + threadIdx.x] = __float2half_rn(t[threadIdx.x][i]);
}

// ---------------------------------------------------------------------------
// fp16 tensor GEMM (R11/R12 winner, unchanged): tile 128x128x64, 4 warps
// (2Mx2N), warp tile 64x64, 128 threads, occ 2, 3-stage ring, swz128.
// ---------------------------------------------------------------------------
#define G_STG 32768
#define G_SMEM (3 * G_STG)

template <bool OUTHALF, bool BIAS>
__global__ __launch_bounds__(128, 2)
void hgemm_kernel(const __half* __restrict__ A, const __half* __restrict__ B,
                  const float* __restrict__ bias, void* __restrict__ Cv,
                  int M, int N, int K) {
    extern __shared__ char sm[];
    const uint32_t smb = smem_u32(sm);
    const int tid = threadIdx.x;
    const int warp = tid >> 5;
    const int lane = tid & 31;
    const int g = lane >> 2;
    const int tig = lane & 3;
    const int wm = (warp >> 1) * 64;
    const int wn = (warp & 1) * 64;
    const int bm = blockIdx.y * 128;
    const int bn = blockIdx.x * 128;

    const int a_row = wm + (lane & 15);
    const int a_cc = (lane >> 4);
    const int b_row = wn + (lane & 7) + ((lane >> 4) & 1) * 8;
    const int b_cc = (lane >> 3) & 1;

    float acc[4][8][4];
#pragma unroll
    for (int mi = 0; mi < 4; mi++)
#pragma unroll
        for (int nj = 0; nj < 8; nj++)
#pragma unroll
            for (int r = 0; r < 4; r++) acc[mi][nj][r] = 0.0f;

    auto fill = [&](int t) {
        const uint32_t sa = smb + (t % 3) * G_STG;
        const uint32_t sb = sa + 128 * 128;
        const int k0 = t * 64;
#pragma unroll
        for (int i = 0; i < 8; i++) {
            int idx = tid + i * 128;
            int r = idx >> 3, c = idx & 7;
            cp16(sa + swz128(r, c), &A[(size_t)(bm + r) * K + k0 + c * 8]);
        }
#pragma unroll
        for (int i = 0; i < 8; i++) {
            int idx = tid + i * 128;
            int r = idx >> 3, c = idx & 7;
            cp16(sb + swz128(r, c), &B[(size_t)(bn + r) * K + k0 + c * 8]);
        }
    };

    const int T = K / 64;
    fill(0); cp_commit();
    fill(1); cp_commit();

    for (int t = 0; t < T; t++) {
        cp_wait<1>();
        __syncthreads();
        if (t + 2 < T) fill(t + 2);
        cp_commit();

        const uint32_t sa = smb + (t % 3) * G_STG;
        const uint32_t sb = sa + 128 * 128;
#pragma unroll
        for (int kf = 0; kf < 4; kf++) {
            const int cc = kf * 2;
            uint32_t a[4][4];
#pragma unroll
            for (int mi = 0; mi < 4; mi++) {
                int r = a_row + mi * 16;
                ldsm_x4(a[mi][0], a[mi][1], a[mi][2], a[mi][3],
                        sa + swz128(r, cc + a_cc));
            }
            uint32_t b[8][2];
#pragma unroll
            for (int njp = 0; njp < 4; njp++) {
                int r = b_row + njp * 16;
                ldsm_x4(b[njp * 2][0], b[njp * 2][1], b[njp * 2 + 1][0], b[njp * 2 + 1][1],
                        sb + swz128(r, cc + b_cc));
            }
#pragma unroll
            for (int mi = 0; mi < 4; mi++)
#pragma unroll
                for (int nj = 0; nj < 8; nj++) mma_f16(acc[mi][nj], a[mi], b[nj]);
        }
    }

    // epilogue
#pragma unroll
    for (int mi = 0; mi < 4; mi++) {
        int r0 = bm + wm + mi * 16 + g;
#pragma unroll
        for (int nj = 0; nj < 8; nj++) {
            int n = bn + wn + nj * 8 + tig * 2;
            float c0 = acc[mi][nj][0], c1 = acc[mi][nj][1];
            float c2 = acc[mi][nj][2], c3 = acc[mi][nj][3];
            if (BIAS) {
                float b0 = bias[n], b1 = bias[n + 1];
                c0 += b0; c1 += b1; c2 += b0; c3 += b1;
            }
            if (OUTHALF) {
                __half* C = (__half*)Cv;
                *reinterpret_cast<__half2*>(&C[(size_t)r0 * N + n]) =
                    __floats2half2_rn(c0, c1);
                *reinterpret_cast<__half2*>(&C[(size_t)(r0 + 8) * N + n]) =
                    __floats2half2_rn(c2, c3);
            } else {
                float* C = (float*)Cv;
                *reinterpret_cast<float2*>(&C[(size_t)r0 * N + n]) = make_float2(c0, c1);
                *reinterpret_cast<float2*>(&C[(size_t)(r0 + 8) * N + n]) = make_float2(c2, c3);
            }
        }
    }
}

// ---------------------------------------------------------------------------
// Block-diagonal causal attention, SPLIT: 2 CTAs per block (64 q-rows each),
// 128 threads / 4 warps (2Mx2N, warp tile 32x64), occ 2.
// smem: S fp32 64x132 (33792) | 2 x 32KB stage ring (QK: Q@0 8KB + K@8192
// 16KB; V: full 32KB, swz256) | P fp16 swz256 64x256B (16384). Total 115712.
// Softmax: 2 threads/row, shfl-pair reductions, no register spill array.
// ---------------------------------------------------------------------------
#define A2_STG_OFF 33792
#define A2_P_OFF   (33792 + 2 * 32768)            // 99328
#define A2_SMEM    (A2_P_OFF + 64 * 256)          // 115712

__global__ __launch_bounds__(128, 2)
void attn_tc_kernel(const __half* __restrict__ qkv, __half* __restrict__ attn_out) {
    extern __shared__ char sm[];
    float* S = (float*)sm;                         // 64 x 132 fp32
    const uint32_t smb = smem_u32(sm);
    const uint32_t stg0 = smb + A2_STG_OFF;
    const uint32_t pb = smb + A2_P_OFF;

    const int blk = blockIdx.x >> 1;               // 0..127
    const int half = blockIdx.x & 1;               // which 64-row half
    const __half* qp = qkv + (size_t)blk * 128 * QKV_LD + (size_t)half * 64 * QKV_LD;
    const __half* kp = qkv + (size_t)blk * 128 * QKV_LD + HH;
    const __half* vp = qkv + (size_t)blk * 128 * QKV_LD + 2 * HH;

    const int tid = threadIdx.x;
    const int warp = tid >> 5;
    const int lane = tid & 31;
    const int g = lane >> 2;
    const int tig = lane & 3;
    const int wm = (warp >> 1) * 32;               // 0 / 32
    const int wn = (warp & 1) * 64;                // 0 / 64

    const int a_row = wm + (lane & 15);            // 0..63
    const int a_cc = lane >> 4;
    const int b_row = wn + (lane & 7) + ((lane >> 4) & 1) * 8;
    const int b_cc = (lane >> 3) & 1;

    // ---------------- Phase 1: S = Q(64) @ K(128)^T ----------------
    float acc[2][8][4];
#pragma unroll
    for (int mi = 0; mi < 2; mi++)
#pragma unroll
        for (int nj = 0; nj < 8; nj++)
#pragma unroll
            for (int r = 0; r < 4; r++) acc[mi][nj][r] = 0.0f;

    auto fillQK = [&](int t) {
        const uint32_t qs = stg0 + (t & 1) * 32768;
        const uint32_t ks = qs + 8192;
        const int k0 = t * 64;
#pragma unroll
        for (int i = 0; i < 4; i++) {              // Q: 64 rows x 8 chunks
            int idx = tid + i * 128;
            int r = idx >> 3, c = idx & 7;
            cp16(qs + swz128(r, c), &qp[(size_t)r * QKV_LD + k0 + c * 8]);
        }
#pragma unroll
        for (int i = 0; i < 8; i++) {              // K: 128 rows x 8 chunks
            int idx = tid + i * 128;
            int r = idx >> 3, c = idx & 7;
            cp16(ks + swz128(r, c), &kp[(size_t)r * QKV_LD + k0 + c * 8]);
        }
    };

    fillQK(0); cp_commit();
    for (int t = 0; t < 16; t++) {
        cp_wait<0>();
        __syncthreads();
        if (t + 1 < 16) fillQK(t + 1);
        cp_commit();

        const uint32_t qs = stg0 + (t & 1) * 32768;
        const uint32_t ks = qs + 8192;
#pragma unroll
        for (int kf = 0; kf < 4; kf++) {
            const int cc = kf * 2;
            uint32_t a[2][4];
#pragma unroll
            for (int mi = 0; mi < 2; mi++) {
                int r = a_row + mi * 16;
                ldsm_x4(a[mi][0], a[mi][1], a[mi][2], a[mi][3],
                        qs + swz128(r, cc + a_cc));
            }
            uint32_t b[8][2];
#pragma unroll
            for (int njp = 0; njp < 4; njp++) {
                int r = b_row + njp * 16;
                ldsm_x4(b[njp * 2][0], b[njp * 2][1], b[njp * 2 + 1][0], b[njp * 2 + 1][1],
                        ks + swz128(r, cc + b_cc));
            }
#pragma unroll
            for (int mi = 0; mi < 2; mi++)
#pragma unroll
                for (int nj = 0; nj < 8; nj++) mma_f16(acc[mi][nj], a[mi], b[nj]);
        }
    }

    // scale + causal mask -> S (row index local 0..63; global q row = half*64+r)
    const float scale = 0.03125f;
    const int qbase = half * 64;
#pragma unroll
    for (int mi = 0; mi < 2; mi++) {
        int r0 = wm + mi * 16 + g;
        int r1 = r0 + 8;
#pragma unroll
        for (int nj = 0; nj < 8; nj++) {
            int c = wn + nj * 8 + tig * 2;
            S[r0 * 132 + c]     = (c     <= qbase + r0) ? acc[mi][nj][0] * scale : -INFINITY;
            S[r0 * 132 + c + 1] = (c + 1 <= qbase + r0) ? acc[mi][nj][1] * scale : -INFINITY;
            S[r1 * 132 + c]     = (c     <= qbase + r1) ? acc[mi][nj][2] * scale : -INFINITY;
            S[r1 * 132 + c + 1] = (c + 1 <= qbase + r1) ? acc[mi][nj][3] * scale : -INFINITY;
        }
    }
    __syncthreads();

    // softmax: 2 threads per row (64 rows, 128 threads); pair-shfl reductions
    {
        const int row = tid >> 1;
        const int hk = (tid & 1) * 64;
        float* rp = S + row * 132 + hk;
        float m = -INFINITY;
#pragma unroll 4
        for (int k = 0; k < 64; k++) m = fmaxf(m, rp[k]);
        m = fmaxf(m, __shfl_xor_sync(0xffffffffu, m, 1));
        float s = 0.0f;
#pragma unroll 4
        for (int k = 0; k < 64; k++) {
            float e = expf(rp[k] - m);
            rp[k] = e;
            s += e;
        }
        s += __shfl_xor_sync(0xffffffffu, s, 1);
        float inv = 1.0f / (s + 1e-6f);
        // write P (fp16, swz256 layout: row r, chunk = col/8)
#pragma unroll
        for (int k = 0; k < 64; k += 8) {
            uint32_t base = pb + swz256(row, (hk + k) >> 3);
            __half2* dst = reinterpret_cast<__half2*>(sm + (base - smb));
#pragma unroll
            for (int j = 0; j < 4; j++)
                dst[j] = __floats2half2_rn(rp[k + 2 * j] * inv, rp[k + 2 * j + 1] * inv);
        }
    }
    __syncthreads();

    // ---------------- Phase 2: O = P(64x128) @ V(128x1024) ------------------
    auto fillV = [&](int c) {
        const uint32_t vs = stg0 + (c & 1) * 32768;
#pragma unroll
        for (int i = 0; i < 16; i++) {             // V: 128 rows x 16 chunks
            int idx = tid + i * 128;
            int r = idx >> 4, ch = idx & 15;
            cp16(vs + swz256(r, ch), &vp[(size_t)r * QKV_LD + c * 128 + ch * 8]);
        }
    };

    const int p_row = wm + (lane & 15);
    const int p_cc = lane >> 4;
    const int v_lrow = (lane & 7) + ((lane >> 3) & 1) * 8;
    const int v_colp = wn / 8 + ((lane >> 4) & 1);

    fillV(0); cp_commit();
    for (int c = 0; c < 8; c++) {
        cp_wait<0>();
        __syncthreads();
        if (c + 1 < 8) fillV(c + 1);
        cp_commit();

        const uint32_t vs = stg0 + (c & 1) * 32768;
        float o[2][8][4];
#pragma unroll
        for (int mi = 0; mi < 2; mi++)
#pragma unroll
            for (int nj = 0; nj < 8; nj++)
#pragma unroll
                for (int r = 0; r < 4; r++) o[mi][nj][r] = 0.0f;

#pragma unroll
        for (int kk = 0; kk < 8; kk++) {
            uint32_t a[2][4];
#pragma unroll
            for (int mi = 0; mi < 2; mi++)
                ldsm_x4(a[mi][0], a[mi][1], a[mi][2], a[mi][3],
                        pb + swz256(p_row + mi * 16, kk * 2 + p_cc));
            uint32_t b[8][2];
#pragma unroll
            for (int np = 0; np < 4; np++) {
                int krow = kk * 16 + v_lrow;
                int chunk = v_colp + np * 2;
                ldsm_x4_t(b[np * 2][0], b[np * 2][1], b[np * 2 + 1][0], b[np * 2 + 1][1],
                          vs + swz256(krow, chunk));
            }
#pragma unroll
            for (int mi = 0; mi < 2; mi++)
#pragma unroll
                for (int nj = 0; nj < 8; nj++) mma_f16(o[mi][nj], a[mi], b[nj]);
        }

        // write output chunk (fp16)
#pragma unroll
        for (int mi = 0; mi < 2; mi++) {
            int r0 = blk * 128 + half * 64 + wm + mi * 16 + g;
#pragma unroll
            for (int nj = 0; nj < 8; nj++) {
                int col = c * 128 + wn + nj * 8 + tig * 2;
                *reinterpret_cast<__half2*>(&attn_out[(size_t)r0 * HH + col]) =
                    __floats2half2_rn(o[mi][nj][0], o[mi][nj][1]);
                *reinterpret_cast<__half2*>(&attn_out[(size_t)(r0 + 8) * HH + col]) =
                    __floats2half2_rn(o[mi][nj][2], o[mi][nj][3]);
            }
        }
    }
}

// ---------------------------------------------------------------------------
extern "C" void kernel_launch(void* const* d_in, const int* in_sizes, int n_in,
                              void* d_out, int out_size) {
    const float* x    = (const float*)d_in[0];
    const float* Wqkv = (const float*)d_in[1];
    const float* Wout = (const float*)d_in[2];
    const float* bout = (const float*)d_in[3];
    float* out = (float*)d_out;

    __half *qkvh, *attnh, *xh, *wqkvt, *wouth;
    cudaGetSymbolAddress((void**)&qkvh, g_qkvh);
    cudaGetSymbolAddress((void**)&attnh, g_attnh);
    cudaGetSymbolAddress((void**)&xh, g_xh);
    cudaGetSymbolAddress((void**)&wqkvt, g_wqkvt);
    cudaGetSymbolAddress((void**)&wouth, g_wouth);

    // conversions
    cvt_half_kernel<<<2048, 256>>>(x, xh, (NTOK * EE) / 4);
    transpose_cvt_kernel<<<dim3(QKV_LD / 32, EE / 32), dim3(32, 8)>>>(
        Wqkv, wqkvt, EE, QKV_LD);
    cvt_half_kernel<<<512, 256>>>(Wout, wouth, (HH * HH) / 4);

    // GEMM1: qkvh = xh @ wqkvt^T   [16384, 3072] (fp16 out)
    {
        cudaFuncSetAttribute(hgemm_kernel<true, false>,
                             cudaFuncAttributeMaxDynamicSharedMemorySize, G_SMEM);
        dim3 grid(QKV_LD / 128, NTOK / 128);   // (24, 128)
        hgemm_kernel<true, false><<<grid, 128, G_SMEM>>>(
            xh, wqkvt, nullptr, qkvh, NTOK, QKV_LD, EE);
    }

    // Attention: 256 CTAs (2 per block), 128 threads, occ 2
    {
        cudaFuncSetAttribute(attn_tc_kernel,
                             cudaFuncAttributeMaxDynamicSharedMemorySize, A2_SMEM);
        attn_tc_kernel<<<BB * (SS / 128) * 2, 128, A2_SMEM>>>(qkvh, attnh);
    }

    // GEMM3: out = attnh @ wouth^T + bout   [16384, 1024] (fp32 out)
    {
        cudaFuncSetAttribute(hgemm_kernel<false, true>,
                             cudaFuncAttributeMaxDynamicSharedMemorySize, G_SMEM);
        dim3 grid(HH / 128, NTOK / 128);       // (8, 128)
        hgemm_kernel<false, true><<<grid, 128, G_SMEM>>>(
            attnh, wouth, bout, out, NTOK, HH, HH);
    }
}

// round 15
// speedup vs baseline: 1.0009x; 1.0009x over previous
#include <cuda_runtime.h>
#include <cuda_fp16.h>
#include <math.h>
#include <stdint.h>

// Problem constants
#define BB 4
#define SS 4096
#define EE 1024
#define HH 1024
#define NTOK (BB * SS)            // 16384
#define QKV_LD (3 * HH)           // 3072

// Scratch (device globals)
__device__ __half g_qkvh[(size_t)NTOK * QKV_LD];   // GEMM1 out / attn in (fp16)
__device__ __half g_attnh[(size_t)NTOK * HH];      // attn out / GEMM3 A (fp16)
__device__ __half g_xh[(size_t)NTOK * EE];         // x fp16
__device__ __half g_wqkvt[(size_t)QKV_LD * EE];    // W_qkv^T fp16 [3072][1024]
__device__ __half g_wouth[(size_t)HH * HH];        // W_out fp16 [1024][1024] ([n][k])

// ---------------------------------------------------------------------------
// helpers
// ---------------------------------------------------------------------------
__device__ __forceinline__ uint32_t smem_u32(const void* p) {
    return (uint32_t)__cvta_generic_to_shared(p);
}
__device__ __forceinline__ void cp16(uint32_t dst, const void* g) {
    asm volatile("cp.async.cg.shared.global [%0], [%1], 16;\n" :: "r"(dst), "l"(g));
}
__device__ __forceinline__ void cp_commit() {
    asm volatile("cp.async.commit_group;\n");
}
template <int N> __device__ __forceinline__ void cp_wait() {
    asm volatile("cp.async.wait_group %0;\n" :: "n"(N));
}

// fp16 mma, fp32 accumulate: D = A(16x16) * B(16x8) + D
__device__ __forceinline__ void mma_f16(float c[4], const uint32_t a[4],
                                        const uint32_t b[2]) {
    asm volatile(
        "mma.sync.aligned.m16n8k16.row.col.f32.f16.f16.f32 "
        "{%0,%1,%2,%3}, {%4,%5,%6,%7}, {%8,%9}, {%0,%1,%2,%3};\n"
        : "+f"(c[0]), "+f"(c[1]), "+f"(c[2]), "+f"(c[3])
        : "r"(a[0]), "r"(a[1]), "r"(a[2]), "r"(a[3]), "r"(b[0]), "r"(b[1]));
}

__device__ __forceinline__ void ldsm_x4(uint32_t& r0, uint32_t& r1,
                                        uint32_t& r2, uint32_t& r3, uint32_t a) {
    asm volatile("ldmatrix.sync.aligned.m8n8.x4.shared.b16 {%0,%1,%2,%3}, [%4];"
                 : "=r"(r0), "=r"(r1), "=r"(r2), "=r"(r3) : "r"(a));
}
__device__ __forceinline__ void ldsm_x4_t(uint32_t& r0, uint32_t& r1,
                                          uint32_t& r2, uint32_t& r3, uint32_t a) {
    asm volatile("ldmatrix.sync.aligned.m8n8.x4.trans.shared.b16 {%0,%1,%2,%3}, [%4];"
                 : "=r"(r0), "=r"(r1), "=r"(r2), "=r"(r3) : "r"(a));
}

// XOR swizzle, 128B rows (8 x 16B chunks): chunk c of row r at c^(r&7)
__device__ __forceinline__ uint32_t swz128(int r, int c) {
    return (uint32_t)(r * 128 + ((c ^ (r & 7)) << 4));
}
// XOR swizzle, 256B rows (16 x 16B chunks)
__device__ __forceinline__ uint32_t swz256(int r, int c) {
    return (uint32_t)(r * 256 + ((c ^ (r & 7)) << 4));
}

// ---------------------------------------------------------------------------
// conversions
// ---------------------------------------------------------------------------
__global__ void cvt_half_kernel(const float* __restrict__ in,
                                __half* __restrict__ out, int n4) {
    int i = blockIdx.x * blockDim.x + threadIdx.x;
    int stride = gridDim.x * blockDim.x;
    for (; i < n4; i += stride) {
        float4 v = reinterpret_cast<const float4*>(in)[i];
        reinterpret_cast<__half2*>(out)[i * 2 + 0] = __floats2half2_rn(v.x, v.y);
        reinterpret_cast<__half2*>(out)[i * 2 + 1] = __floats2half2_rn(v.z, v.w);
    }
}

__global__ void transpose_cvt_kernel(const float* __restrict__ in,
                                     __half* __restrict__ out, int R, int C) {
    __shared__ float t[32][33];
    int bx = blockIdx.x * 32;   // C
    int by = blockIdx.y * 32;   // R
#pragma unroll
    for (int i = threadIdx.y; i < 32; i += 8)
        t[i][threadIdx.x] = in[(size_t)(by + i) * C + bx + threadIdx.x];
    __syncthreads();
#pragma unroll
    for (int i = threadIdx.y; i < 32; i += 8)
        out[(size_t)(bx + i) * R + by + threadIdx.x] = __float2half_rn(t[threadIdx.x][i]);
}

// ---------------------------------------------------------------------------
// fp16 tensor GEMM (R11/R12 winner, unchanged): tile 128x128x64, 4 warps
// (2Mx2N), warp tile 64x64, 128 threads, occ 2, 3-stage ring, swz128.
// ---------------------------------------------------------------------------
#define G_STG 32768
#define G_SMEM (3 * G_STG)

template <bool OUTHALF, bool BIAS>
__global__ __launch_bounds__(128, 2)
void hgemm_kernel(const __half* __restrict__ A, const __half* __restrict__ B,
                  const float* __restrict__ bias, void* __restrict__ Cv,
                  int M, int N, int K) {
    extern __shared__ char sm[];
    const uint32_t smb = smem_u32(sm);
    const int tid = threadIdx.x;
    const int warp = tid >> 5;
    const int lane = tid & 31;
    const int g = lane >> 2;
    const int tig = lane & 3;
    const int wm = (warp >> 1) * 64;
    const int wn = (warp & 1) * 64;
    const int bm = blockIdx.y * 128;
    const int bn = blockIdx.x * 128;

    const int a_row = wm + (lane & 15);
    const int a_cc = (lane >> 4);
    const int b_row = wn + (lane & 7) + ((lane >> 4) & 1) * 8;
    const int b_cc = (lane >> 3) & 1;

    float acc[4][8][4];
#pragma unroll
    for (int mi = 0; mi < 4; mi++)
#pragma unroll
        for (int nj = 0; nj < 8; nj++)
#pragma unroll
            for (int r = 0; r < 4; r++) acc[mi][nj][r] = 0.0f;

    auto fill = [&](int t) {
        const uint32_t sa = smb + (t % 3) * G_STG;
        const uint32_t sb = sa + 128 * 128;
        const int k0 = t * 64;
#pragma unroll
        for (int i = 0; i < 8; i++) {
            int idx = tid + i * 128;
            int r = idx >> 3, c = idx & 7;
            cp16(sa + swz128(r, c), &A[(size_t)(bm + r) * K + k0 + c * 8]);
        }
#pragma unroll
        for (int i = 0; i < 8; i++) {
            int idx = tid + i * 128;
            int r = idx >> 3, c = idx & 7;
            cp16(sb + swz128(r, c), &B[(size_t)(bn + r) * K + k0 + c * 8]);
        }
    };

    const int T = K / 64;
    fill(0); cp_commit();
    fill(1); cp_commit();

    for (int t = 0; t < T; t++) {
        cp_wait<1>();
        __syncthreads();
        if (t + 2 < T) fill(t + 2);
        cp_commit();

        const uint32_t sa = smb + (t % 3) * G_STG;
        const uint32_t sb = sa + 128 * 128;
#pragma unroll
        for (int kf = 0; kf < 4; kf++) {
            const int cc = kf * 2;
            uint32_t a[4][4];
#pragma unroll
            for (int mi = 0; mi < 4; mi++) {
                int r = a_row + mi * 16;
                ldsm_x4(a[mi][0], a[mi][1], a[mi][2], a[mi][3],
                        sa + swz128(r, cc + a_cc));
            }
            uint32_t b[8][2];
#pragma unroll
            for (int njp = 0; njp < 4; njp++) {
                int r = b_row + njp * 16;
                ldsm_x4(b[njp * 2][0], b[njp * 2][1], b[njp * 2 + 1][0], b[njp * 2 + 1][1],
                        sb + swz128(r, cc + b_cc));
            }
#pragma unroll
            for (int mi = 0; mi < 4; mi++)
#pragma unroll
                for (int nj = 0; nj < 8; nj++) mma_f16(acc[mi][nj], a[mi], b[nj]);
        }
    }

    // epilogue
#pragma unroll
    for (int mi = 0; mi < 4; mi++) {
        int r0 = bm + wm + mi * 16 + g;
#pragma unroll
        for (int nj = 0; nj < 8; nj++) {
            int n = bn + wn + nj * 8 + tig * 2;
            float c0 = acc[mi][nj][0], c1 = acc[mi][nj][1];
            float c2 = acc[mi][nj][2], c3 = acc[mi][nj][3];
            if (BIAS) {
                float b0 = bias[n], b1 = bias[n + 1];
                c0 += b0; c1 += b1; c2 += b0; c3 += b1;
            }
            if (OUTHALF) {
                __half* C = (__half*)Cv;
                *reinterpret_cast<__half2*>(&C[(size_t)r0 * N + n]) =
                    __floats2half2_rn(c0, c1);
                *reinterpret_cast<__half2*>(&C[(size_t)(r0 + 8) * N + n]) =
                    __floats2half2_rn(c2, c3);
            } else {
                float* C = (float*)Cv;
                *reinterpret_cast<float2*>(&C[(size_t)r0 * N + n]) = make_float2(c0, c1);
                *reinterpret_cast<float2*>(&C[(size_t)(r0 + 8) * N + n]) = make_float2(c2, c3);
            }
        }
    }
}

// ---------------------------------------------------------------------------
// Block-diagonal causal attention, SPLIT: 2 CTAs per block (64 q-rows each),
// 128 threads / 4 warps (2Mx2N, warp tile 32x64), occ 2.
// smem: S fp32 64x132 (33792) | 2 x 32KB stage ring (QK: Q@0 8KB + K@8192
// 16KB; V: full 32KB, swz256) | P fp16 swz256 64x256B (16384). Total 115712.
// Softmax: 2 threads/row, shfl-pair reductions, no register spill array.
// ---------------------------------------------------------------------------
#define A2_STG_OFF 33792
#define A2_P_OFF   (33792 + 2 * 32768)            // 99328
#define A2_SMEM    (A2_P_OFF + 64 * 256)          // 115712

__global__ __launch_bounds__(128, 2)
void attn_tc_kernel(const __half* __restrict__ qkv, __half* __restrict__ attn_out) {
    extern __shared__ char sm[];
    float* S = (float*)sm;                         // 64 x 132 fp32
    const uint32_t smb = smem_u32(sm);
    const uint32_t stg0 = smb + A2_STG_OFF;
    const uint32_t pb = smb + A2_P_OFF;

    const int blk = blockIdx.x >> 1;               // 0..127
    const int half = blockIdx.x & 1;               // which 64-row half
    const __half* qp = qkv + (size_t)blk * 128 * QKV_LD + (size_t)half * 64 * QKV_LD;
    const __half* kp = qkv + (size_t)blk * 128 * QKV_LD + HH;
    const __half* vp = qkv + (size_t)blk * 128 * QKV_LD + 2 * HH;

    const int tid = threadIdx.x;
    const int warp = tid >> 5;
    const int lane = tid & 31;
    const int g = lane >> 2;
    const int tig = lane & 3;
    const int wm = (warp >> 1) * 32;               // 0 / 32
    const int wn = (warp & 1) * 64;                // 0 / 64

    const int a_row = wm + (lane & 15);            // 0..63
    const int a_cc = lane >> 4;
    const int b_row = wn + (lane & 7) + ((lane >> 4) & 1) * 8;
    const int b_cc = (lane >> 3) & 1;

    // ---------------- Phase 1: S = Q(64) @ K(128)^T ----------------
    float acc[2][8][4];
#pragma unroll
    for (int mi = 0; mi < 2; mi++)
#pragma unroll
        for (int nj = 0; nj < 8; nj++)
#pragma unroll
            for (int r = 0; r < 4; r++) acc[mi][nj][r] = 0.0f;

    auto fillQK = [&](int t) {
        const uint32_t qs = stg0 + (t & 1) * 32768;
        const uint32_t ks = qs + 8192;
        const int k0 = t * 64;
#pragma unroll
        for (int i = 0; i < 4; i++) {              // Q: 64 rows x 8 chunks
            int idx = tid + i * 128;
            int r = idx >> 3, c = idx & 7;
            cp16(qs + swz128(r, c), &qp[(size_t)r * QKV_LD + k0 + c * 8]);
        }
#pragma unroll
        for (int i = 0; i < 8; i++) {              // K: 128 rows x 8 chunks
            int idx = tid + i * 128;
            int r = idx >> 3, c = idx & 7;
            cp16(ks + swz128(r, c), &kp[(size_t)r * QKV_LD + k0 + c * 8]);
        }
    };

    fillQK(0); cp_commit();
    for (int t = 0; t < 16; t++) {
        cp_wait<0>();
        __syncthreads();
        if (t + 1 < 16) fillQK(t + 1);
        cp_commit();

        const uint32_t qs = stg0 + (t & 1) * 32768;
        const uint32_t ks = qs + 8192;
#pragma unroll
        for (int kf = 0; kf < 4; kf++) {
            const int cc = kf * 2;
            uint32_t a[2][4];
#pragma unroll
            for (int mi = 0; mi < 2; mi++) {
                int r = a_row + mi * 16;
                ldsm_x4(a[mi][0], a[mi][1], a[mi][2], a[mi][3],
                        qs + swz128(r, cc + a_cc));
            }
            uint32_t b[8][2];
#pragma unroll
            for (int njp = 0; njp < 4; njp++) {
                int r = b_row + njp * 16;
                ldsm_x4(b[njp * 2][0], b[njp * 2][1], b[njp * 2 + 1][0], b[njp * 2 + 1][1],
                        ks + swz128(r, cc + b_cc));
            }
#pragma unroll
            for (int mi = 0; mi < 2; mi++)
#pragma unroll
                for (int nj = 0; nj < 8; nj++) mma_f16(acc[mi][nj], a[mi], b[nj]);
        }
    }

    // scale + causal mask -> S (row index local 0..63; global q row = half*64+r)
    const float scale = 0.03125f;
    const int qbase = half * 64;
#pragma unroll
    for (int mi = 0; mi < 2; mi++) {
        int r0 = wm + mi * 16 + g;
        int r1 = r0 + 8;
#pragma unroll
        for (int nj = 0; nj < 8; nj++) {
            int c = wn + nj * 8 + tig * 2;
            S[r0 * 132 + c]     = (c     <= qbase + r0) ? acc[mi][nj][0] * scale : -INFINITY;
            S[r0 * 132 + c + 1] = (c + 1 <= qbase + r0) ? acc[mi][nj][1] * scale : -INFINITY;
            S[r1 * 132 + c]     = (c     <= qbase + r1) ? acc[mi][nj][2] * scale : -INFINITY;
            S[r1 * 132 + c + 1] = (c + 1 <= qbase + r1) ? acc[mi][nj][3] * scale : -INFINITY;
        }
    }
    __syncthreads();

    // softmax: 2 threads per row (64 rows, 128 threads); pair-shfl reductions
    {
        const int row = tid >> 1;
        const int hk = (tid & 1) * 64;
        float* rp = S + row * 132 + hk;
        float m = -INFINITY;
#pragma unroll 4
        for (int k = 0; k < 64; k++) m = fmaxf(m, rp[k]);
        m = fmaxf(m, __shfl_xor_sync(0xffffffffu, m, 1));
        float s = 0.0f;
#pragma unroll 4
        for (int k = 0; k < 64; k++) {
            float e = expf(rp[k] - m);
            rp[k] = e;
            s += e;
        }
        s += __shfl_xor_sync(0xffffffffu, s, 1);
        float inv = 1.0f / (s + 1e-6f);
        // write P (fp16, swz256 layout: row r, chunk = col/8)
#pragma unroll
        for (int k = 0; k < 64; k += 8) {
            uint32_t base = pb + swz256(row, (hk + k) >> 3);
            __half2* dst = reinterpret_cast<__half2*>(sm + (base - smb));
#pragma unroll
            for (int j = 0; j < 4; j++)
                dst[j] = __floats2half2_rn(rp[k + 2 * j] * inv, rp[k + 2 * j + 1] * inv);
        }
    }
    __syncthreads();

    // ---------------- Phase 2: O = P(64x128) @ V(128x1024) ------------------
    auto fillV = [&](int c) {
        const uint32_t vs = stg0 + (c & 1) * 32768;
#pragma unroll
        for (int i = 0; i < 16; i++) {             // V: 128 rows x 16 chunks
            int idx = tid + i * 128;
            int r = idx >> 4, ch = idx & 15;
            cp16(vs + swz256(r, ch), &vp[(size_t)r * QKV_LD + c * 128 + ch * 8]);
        }
    };

    const int p_row = wm + (lane & 15);
    const int p_cc = lane >> 4;
    const int v_lrow = (lane & 7) + ((lane >> 3) & 1) * 8;
    const int v_colp = wn / 8 + ((lane >> 4) & 1);

    fillV(0); cp_commit();
    for (int c = 0; c < 8; c++) {
        cp_wait<0>();
        __syncthreads();
        if (c + 1 < 8) fillV(c + 1);
        cp_commit();

        const uint32_t vs = stg0 + (c & 1) * 32768;
        float o[2][8][4];
#pragma unroll
        for (int mi = 0; mi < 2; mi++)
#pragma unroll
            for (int nj = 0; nj < 8; nj++)
#pragma unroll
                for (int r = 0; r < 4; r++) o[mi][nj][r] = 0.0f;

#pragma unroll
        for (int kk = 0; kk < 8; kk++) {
            uint32_t a[2][4];
#pragma unroll
            for (int mi = 0; mi < 2; mi++)
                ldsm_x4(a[mi][0], a[mi][1], a[mi][2], a[mi][3],
                        pb + swz256(p_row + mi * 16, kk * 2 + p_cc));
            uint32_t b[8][2];
#pragma unroll
            for (int np = 0; np < 4; np++) {
                int krow = kk * 16 + v_lrow;
                int chunk = v_colp + np * 2;
                ldsm_x4_t(b[np * 2][0], b[np * 2][1], b[np * 2 + 1][0], b[np * 2 + 1][1],
                          vs + swz256(krow, chunk));
            }
#pragma unroll
            for (int mi = 0; mi < 2; mi++)
#pragma unroll
                for (int nj = 0; nj < 8; nj++) mma_f16(o[mi][nj], a[mi], b[nj]);
        }

        // write output chunk (fp16)
#pragma unroll
        for (int mi = 0; mi < 2; mi++) {
            int r0 = blk * 128 + half * 64 + wm + mi * 16 + g;
#pragma unroll
            for (int nj = 0; nj < 8; nj++) {
                int col = c * 128 + wn + nj * 8 + tig * 2;
                *reinterpret_cast<__half2*>(&attn_out[(size_t)r0 * HH + col]) =
                    __floats2half2_rn(o[mi][nj][0], o[mi][nj][1]);
                *reinterpret_cast<__half2*>(&attn_out[(size_t)(r0 + 8) * HH + col]) =
                    __floats2half2_rn(o[mi][nj][2], o[mi][nj][3]);
            }
        }
    }
}

// ---------------------------------------------------------------------------
extern "C" void kernel_launch(void* const* d_in, const int* in_sizes, int n_in,
                              void* d_out, int out_size) {
    const float* x    = (const float*)d_in[0];
    const float* Wqkv = (const float*)d_in[1];
    const float* Wout = (const float*)d_in[2];
    const float* bout = (const float*)d_in[3];
    float* out = (float*)d_out;

    __half *qkvh, *attnh, *xh, *wqkvt, *wouth;
    cudaGetSymbolAddress((void**)&qkvh, g_qkvh);
    cudaGetSymbolAddress((void**)&attnh, g_attnh);
    cudaGetSymbolAddress((void**)&xh, g_xh);
    cudaGetSymbolAddress((void**)&wqkvt, g_wqkvt);
    cudaGetSymbolAddress((void**)&wouth, g_wouth);

    // conversions
    cvt_half_kernel<<<2048, 256>>>(x, xh, (NTOK * EE) / 4);
    transpose_cvt_kernel<<<dim3(QKV_LD / 32, EE / 32), dim3(32, 8)>>>(
        Wqkv, wqkvt, EE, QKV_LD);
    cvt_half_kernel<<<512, 256>>>(Wout, wouth, (HH * HH) / 4);

    // GEMM1: qkvh = xh @ wqkvt^T   [16384, 3072] (fp16 out)
    {
        cudaFuncSetAttribute(hgemm_kernel<true, false>,
                             cudaFuncAttributeMaxDynamicSharedMemorySize, G_SMEM);
        dim3 grid(QKV_LD / 128, NTOK / 128);   // (24, 128)
        hgemm_kernel<true, false><<<grid, 128, G_SMEM>>>(
            xh, wqkvt, nullptr, qkvh, NTOK, QKV_LD, EE);
    }

    // Attention: 256 CTAs (2 per block), 128 threads, occ 2
    {
        cudaFuncSetAttribute(attn_tc_kernel,
                             cudaFuncAttributeMaxDynamicSharedMemorySize, A2_SMEM);
        attn_tc_kernel<<<BB * (SS / 128) * 2, 128, A2_SMEM>>>(qkvh, attnh);
    }

    // GEMM3: out = attnh @ wouth^T + bout   [16384, 1024] (fp32 out)
    {
        cudaFuncSetAttribute(hgemm_kernel<false, true>,
                             cudaFuncAttributeMaxDynamicSharedMemorySize, G_SMEM);
        dim3 grid(HH / 128, NTOK / 128);       // (8, 128)
        hgemm_kernel<false, true><<<grid, 128, G_SMEM>>>(
            attnh, wouth, bout, out, NTOK, HH, HH);
    }
}

// round 16
// speedup vs baseline: 1.0022x; 1.0013x over previous
#include <cuda_runtime.h>
#include <cuda_fp16.h>
#include <math.h>
#include <stdint.h>

// Problem constants
#define BB 4
#define SS 4096
#define EE 1024
#define HH 1024
#define NTOK (BB * SS)            // 16384
#define QKV_LD (3 * HH)           // 3072

// Scratch (device globals)
__device__ __half g_qkvh[(size_t)NTOK * QKV_LD];   // GEMM1 out / attn in (fp16)
__device__ __half g_attnh[(size_t)NTOK * HH];      // attn out / GEMM3 A (fp16)
__device__ __half g_xh[(size_t)NTOK * EE];         // x fp16
__device__ __half g_wqkvt[(size_t)QKV_LD * EE];    // W_qkv^T fp16 [3072][1024]
__device__ __half g_wouth[(size_t)HH * HH];        // W_out fp16 [1024][1024] ([n][k])

// ---------------------------------------------------------------------------
// helpers
// ---------------------------------------------------------------------------
__device__ __forceinline__ uint32_t smem_u32(const void* p) {
    return (uint32_t)__cvta_generic_to_shared(p);
}
__device__ __forceinline__ void cp16(uint32_t dst, const void* g) {
    asm volatile("cp.async.cg.shared.global [%0], [%1], 16;\n" :: "r"(dst), "l"(g));
}
__device__ __forceinline__ void cp_commit() {
    asm volatile("cp.async.commit_group;\n");
}
template <int N> __device__ __forceinline__ void cp_wait() {
    asm volatile("cp.async.wait_group %0;\n" :: "n"(N));
}

// fp16 mma, fp32 accumulate: D = A(16x16) * B(16x8) + D
__device__ __forceinline__ void mma_f16(float c[4], const uint32_t a[4],
                                        const uint32_t b[2]) {
    asm volatile(
        "mma.sync.aligned.m16n8k16.row.col.f32.f16.f16.f32 "
        "{%0,%1,%2,%3}, {%4,%5,%6,%7}, {%8,%9}, {%0,%1,%2,%3};\n"
        : "+f"(c[0]), "+f"(c[1]), "+f"(c[2]), "+f"(c[3])
        : "r"(a[0]), "r"(a[1]), "r"(a[2]), "r"(a[3]), "r"(b[0]), "r"(b[1]));
}

__device__ __forceinline__ void ldsm_x4(uint32_t& r0, uint32_t& r1,
                                        uint32_t& r2, uint32_t& r3, uint32_t a) {
    asm volatile("ldmatrix.sync.aligned.m8n8.x4.shared.b16 {%0,%1,%2,%3}, [%4];"
                 : "=r"(r0), "=r"(r1), "=r"(r2), "=r"(r3) : "r"(a));
}
__device__ __forceinline__ void ldsm_x4_t(uint32_t& r0, uint32_t& r1,
                                          uint32_t& r2, uint32_t& r3, uint32_t a) {
    asm volatile("ldmatrix.sync.aligned.m8n8.x4.trans.shared.b16 {%0,%1,%2,%3}, [%4];"
                 : "=r"(r0), "=r"(r1), "=r"(r2), "=r"(r3) : "r"(a));
}

// XOR swizzle, 128B rows (8 x 16B chunks): chunk c of row r at c^(r&7)
__device__ __forceinline__ uint32_t swz128(int r, int c) {
    return (uint32_t)(r * 128 + ((c ^ (r & 7)) << 4));
}
// XOR swizzle, 256B rows (16 x 16B chunks)
__device__ __forceinline__ uint32_t swz256(int r, int c) {
    return (uint32_t)(r * 256 + ((c ^ (r & 7)) << 4));
}

// ---------------------------------------------------------------------------
// conversions
// ---------------------------------------------------------------------------
__global__ void cvt_half_kernel(const float* __restrict__ in,
                                __half* __restrict__ out, int n4) {
    int i = blockIdx.x * blockDim.x + threadIdx.x;
    int stride = gridDim.x * blockDim.x;
    for (; i < n4; i += stride) {
        float4 v = reinterpret_cast<const float4*>(in)[i];
        reinterpret_cast<__half2*>(out)[i * 2 + 0] = __floats2half2_rn(v.x, v.y);
        reinterpret_cast<__half2*>(out)[i * 2 + 1] = __floats2half2_rn(v.z, v.w);
    }
}

__global__ void transpose_cvt_kernel(const float* __restrict__ in,
                                     __half* __restrict__ out, int R, int C) {
    __shared__ float t[32][33];
    int bx = blockIdx.x * 32;   // C
    int by = blockIdx.y * 32;   // R
#pragma unroll
    for (int i = threadIdx.y; i < 32; i += 8)
        t[i][threadIdx.x] = in[(size_t)(by + i) * C + bx + threadIdx.x];
    __syncthreads();
#pragma unroll
    for (int i = threadIdx.y; i < 32; i += 8)
        out[(size_t)(bx + i) * R + by + threadIdx.x] = __float2half_rn(t[threadIdx.x][i]);
}

// ---------------------------------------------------------------------------
// fp16 tensor GEMM (R11/R12 winner, unchanged): tile 128x128x64, 4 warps
// (2Mx2N), warp tile 64x64, 128 threads, occ 2, 3-stage ring, swz128.
// ---------------------------------------------------------------------------
#define G_STG 32768
#define G_SMEM (3 * G_STG)

template <bool OUTHALF, bool BIAS>
__global__ __launch_bounds__(128, 2)
void hgemm_kernel(const __half* __restrict__ A, const __half* __restrict__ B,
                  const float* __restrict__ bias, void* __restrict__ Cv,
                  int M, int N, int K) {
    extern __shared__ char sm[];
    const uint32_t smb = smem_u32(sm);
    const int tid = threadIdx.x;
    const int warp = tid >> 5;
    const int lane = tid & 31;
    const int g = lane >> 2;
    const int tig = lane & 3;
    const int wm = (warp >> 1) * 64;
    const int wn = (warp & 1) * 64;
    const int bm = blockIdx.y * 128;
    const int bn = blockIdx.x * 128;

    const int a_row = wm + (lane & 15);
    const int a_cc = (lane >> 4);
    const int b_row = wn + (lane & 7) + ((lane >> 4) & 1) * 8;
    const int b_cc = (lane >> 3) & 1;

    float acc[4][8][4];
#pragma unroll
    for (int mi = 0; mi < 4; mi++)
#pragma unroll
        for (int nj = 0; nj < 8; nj++)
#pragma unroll
            for (int r = 0; r < 4; r++) acc[mi][nj][r] = 0.0f;

    auto fill = [&](int t) {
        const uint32_t sa = smb + (t % 3) * G_STG;
        const uint32_t sb = sa + 128 * 128;
        const int k0 = t * 64;
#pragma unroll
        for (int i = 0; i < 8; i++) {
            int idx = tid + i * 128;
            int r = idx >> 3, c = idx & 7;
            cp16(sa + swz128(r, c), &A[(size_t)(bm + r) * K + k0 + c * 8]);
        }
#pragma unroll
        for (int i = 0; i < 8; i++) {
            int idx = tid + i * 128;
            int r = idx >> 3, c = idx & 7;
            cp16(sb + swz128(r, c), &B[(size_t)(bn + r) * K + k0 + c * 8]);
        }
    };

    const int T = K / 64;
    fill(0); cp_commit();
    fill(1); cp_commit();

    for (int t = 0; t < T; t++) {
        cp_wait<1>();
        __syncthreads();
        if (t + 2 < T) fill(t + 2);
        cp_commit();

        const uint32_t sa = smb + (t % 3) * G_STG;
        const uint32_t sb = sa + 128 * 128;
#pragma unroll
        for (int kf = 0; kf < 4; kf++) {
            const int cc = kf * 2;
            uint32_t a[4][4];
#pragma unroll
            for (int mi = 0; mi < 4; mi++) {
                int r = a_row + mi * 16;
                ldsm_x4(a[mi][0], a[mi][1], a[mi][2], a[mi][3],
                        sa + swz128(r, cc + a_cc));
            }
            uint32_t b[8][2];
#pragma unroll
            for (int njp = 0; njp < 4; njp++) {
                int r = b_row + njp * 16;
                ldsm_x4(b[njp * 2][0], b[njp * 2][1], b[njp * 2 + 1][0], b[njp * 2 + 1][1],
                        sb + swz128(r, cc + b_cc));
            }
#pragma unroll
            for (int mi = 0; mi < 4; mi++)
#pragma unroll
                for (int nj = 0; nj < 8; nj++) mma_f16(acc[mi][nj], a[mi], b[nj]);
        }
    }

    // epilogue
#pragma unroll
    for (int mi = 0; mi < 4; mi++) {
        int r0 = bm + wm + mi * 16 + g;
#pragma unroll
        for (int nj = 0; nj < 8; nj++) {
            int n = bn + wn + nj * 8 + tig * 2;
            float c0 = acc[mi][nj][0], c1 = acc[mi][nj][1];
            float c2 = acc[mi][nj][2], c3 = acc[mi][nj][3];
            if (BIAS) {
                float b0 = bias[n], b1 = bias[n + 1];
                c0 += b0; c1 += b1; c2 += b0; c3 += b1;
            }
            if (OUTHALF) {
                __half* C = (__half*)Cv;
                *reinterpret_cast<__half2*>(&C[(size_t)r0 * N + n]) =
                    __floats2half2_rn(c0, c1);
                *reinterpret_cast<__half2*>(&C[(size_t)(r0 + 8) * N + n]) =
                    __floats2half2_rn(c2, c3);
            } else {
                float* C = (float*)Cv;
                *reinterpret_cast<float2*>(&C[(size_t)r0 * N + n]) = make_float2(c0, c1);
                *reinterpret_cast<float2*>(&C[(size_t)(r0 + 8) * N + n]) = make_float2(c2, c3);
            }
        }
    }
}

// ---------------------------------------------------------------------------
// Block-diagonal causal attention, SPLIT: 2 CTAs per block (64 q-rows each),
// 128 threads / 4 warps (2Mx2N, warp tile 32x64), occ 2.
// smem: S fp32 64x132 (33792) | 2 x 32KB stage ring (QK: Q@0 8KB + K@8192
// 16KB; V: full 32KB, swz256) | P fp16 swz256 64x256B (16384). Total 115712.
// Softmax: 2 threads/row, shfl-pair reductions, no register spill array.
// ---------------------------------------------------------------------------
#define A2_STG_OFF 33792
#define A2_P_OFF   (33792 + 2 * 32768)            // 99328
#define A2_SMEM    (A2_P_OFF + 64 * 256)          // 115712

__global__ __launch_bounds__(128, 2)
void attn_tc_kernel(const __half* __restrict__ qkv, __half* __restrict__ attn_out) {
    extern __shared__ char sm[];
    float* S = (float*)sm;                         // 64 x 132 fp32
    const uint32_t smb = smem_u32(sm);
    const uint32_t stg0 = smb + A2_STG_OFF;
    const uint32_t pb = smb + A2_P_OFF;

    const int blk = blockIdx.x >> 1;               // 0..127
    const int half = blockIdx.x & 1;               // which 64-row half
    const __half* qp = qkv + (size_t)blk * 128 * QKV_LD + (size_t)half * 64 * QKV_LD;
    const __half* kp = qkv + (size_t)blk * 128 * QKV_LD + HH;
    const __half* vp = qkv + (size_t)blk * 128 * QKV_LD + 2 * HH;

    const int tid = threadIdx.x;
    const int warp = tid >> 5;
    const int lane = tid & 31;
    const int g = lane >> 2;
    const int tig = lane & 3;
    const int wm = (warp >> 1) * 32;               // 0 / 32
    const int wn = (warp & 1) * 64;                // 0 / 64

    const int a_row = wm + (lane & 15);            // 0..63
    const int a_cc = lane >> 4;
    const int b_row = wn + (lane & 7) + ((lane >> 4) & 1) * 8;
    const int b_cc = (lane >> 3) & 1;

    // ---------------- Phase 1: S = Q(64) @ K(128)^T ----------------
    float acc[2][8][4];
#pragma unroll
    for (int mi = 0; mi < 2; mi++)
#pragma unroll
        for (int nj = 0; nj < 8; nj++)
#pragma unroll
            for (int r = 0; r < 4; r++) acc[mi][nj][r] = 0.0f;

    auto fillQK = [&](int t) {
        const uint32_t qs = stg0 + (t & 1) * 32768;
        const uint32_t ks = qs + 8192;
        const int k0 = t * 64;
#pragma unroll
        for (int i = 0; i < 4; i++) {              // Q: 64 rows x 8 chunks
            int idx = tid + i * 128;
            int r = idx >> 3, c = idx & 7;
            cp16(qs + swz128(r, c), &qp[(size_t)r * QKV_LD + k0 + c * 8]);
        }
#pragma unroll
        for (int i = 0; i < 8; i++) {              // K: 128 rows x 8 chunks
            int idx = tid + i * 128;
            int r = idx >> 3, c = idx & 7;
            cp16(ks + swz128(r, c), &kp[(size_t)r * QKV_LD + k0 + c * 8]);
        }
    };

    fillQK(0); cp_commit();
    for (int t = 0; t < 16; t++) {
        cp_wait<0>();
        __syncthreads();
        if (t + 1 < 16) fillQK(t + 1);
        cp_commit();

        const uint32_t qs = stg0 + (t & 1) * 32768;
        const uint32_t ks = qs + 8192;
#pragma unroll
        for (int kf = 0; kf < 4; kf++) {
            const int cc = kf * 2;
            uint32_t a[2][4];
#pragma unroll
            for (int mi = 0; mi < 2; mi++) {
                int r = a_row + mi * 16;
                ldsm_x4(a[mi][0], a[mi][1], a[mi][2], a[mi][3],
                        qs + swz128(r, cc + a_cc));
            }
            uint32_t b[8][2];
#pragma unroll
            for (int njp = 0; njp < 4; njp++) {
                int r = b_row + njp * 16;
                ldsm_x4(b[njp * 2][0], b[njp * 2][1], b[njp * 2 + 1][0], b[njp * 2 + 1][1],
                        ks + swz128(r, cc + b_cc));
            }
#pragma unroll
            for (int mi = 0; mi < 2; mi++)
#pragma unroll
                for (int nj = 0; nj < 8; nj++) mma_f16(acc[mi][nj], a[mi], b[nj]);
        }
    }

    // scale + causal mask -> S (row index local 0..63; global q row = half*64+r)
    const float scale = 0.03125f;
    const int qbase = half * 64;
#pragma unroll
    for (int mi = 0; mi < 2; mi++) {
        int r0 = wm + mi * 16 + g;
        int r1 = r0 + 8;
#pragma unroll
        for (int nj = 0; nj < 8; nj++) {
            int c = wn + nj * 8 + tig * 2;
            S[r0 * 132 + c]     = (c     <= qbase + r0) ? acc[mi][nj][0] * scale : -INFINITY;
            S[r0 * 132 + c + 1] = (c + 1 <= qbase + r0) ? acc[mi][nj][1] * scale : -INFINITY;
            S[r1 * 132 + c]     = (c     <= qbase + r1) ? acc[mi][nj][2] * scale : -INFINITY;
            S[r1 * 132 + c + 1] = (c + 1 <= qbase + r1) ? acc[mi][nj][3] * scale : -INFINITY;
        }
    }
    __syncthreads();

    // softmax: 2 threads per row (64 rows, 128 threads); pair-shfl reductions
    {
        const int row = tid >> 1;
        const int hk = (tid & 1) * 64;
        float* rp = S + row * 132 + hk;
        float m = -INFINITY;
#pragma unroll 4
        for (int k = 0; k < 64; k++) m = fmaxf(m, rp[k]);
        m = fmaxf(m, __shfl_xor_sync(0xffffffffu, m, 1));
        float s = 0.0f;
#pragma unroll 4
        for (int k = 0; k < 64; k++) {
            float e = expf(rp[k] - m);
            rp[k] = e;
            s += e;
        }
        s += __shfl_xor_sync(0xffffffffu, s, 1);
        float inv = 1.0f / (s + 1e-6f);
        // write P (fp16, swz256 layout: row r, chunk = col/8)
#pragma unroll
        for (int k = 0; k < 64; k += 8) {
            uint32_t base = pb + swz256(row, (hk + k) >> 3);
            __half2* dst = reinterpret_cast<__half2*>(sm + (base - smb));
#pragma unroll
            for (int j = 0; j < 4; j++)
                dst[j] = __floats2half2_rn(rp[k + 2 * j] * inv, rp[k + 2 * j + 1] * inv);
        }
    }
    __syncthreads();

    // ---------------- Phase 2: O = P(64x128) @ V(128x1024) ------------------
    auto fillV = [&](int c) {
        const uint32_t vs = stg0 + (c & 1) * 32768;
#pragma unroll
        for (int i = 0; i < 16; i++) {             // V: 128 rows x 16 chunks
            int idx = tid + i * 128;
            int r = idx >> 4, ch = idx & 15;
            cp16(vs + swz256(r, ch), &vp[(size_t)r * QKV_LD + c * 128 + ch * 8]);
        }
    };

    const int p_row = wm + (lane & 15);
    const int p_cc = lane >> 4;
    const int v_lrow = (lane & 7) + ((lane >> 3) & 1) * 8;
    const int v_colp = wn / 8 + ((lane >> 4) & 1);

    fillV(0); cp_commit();
    for (int c = 0; c < 8; c++) {
        cp_wait<0>();
        __syncthreads();
        if (c + 1 < 8) fillV(c + 1);
        cp_commit();

        const uint32_t vs = stg0 + (c & 1) * 32768;
        float o[2][8][4];
#pragma unroll
        for (int mi = 0; mi < 2; mi++)
#pragma unroll
            for (int nj = 0; nj < 8; nj++)
#pragma unroll
                for (int r = 0; r < 4; r++) o[mi][nj][r] = 0.0f;

#pragma unroll
        for (int kk = 0; kk < 8; kk++) {
            uint32_t a[2][4];
#pragma unroll
            for (int mi = 0; mi < 2; mi++)
                ldsm_x4(a[mi][0], a[mi][1], a[mi][2], a[mi][3],
                        pb + swz256(p_row + mi * 16, kk * 2 + p_cc));
            uint32_t b[8][2];
#pragma unroll
            for (int np = 0; np < 4; np++) {
                int krow = kk * 16 + v_lrow;
                int chunk = v_colp + np * 2;
                ldsm_x4_t(b[np * 2][0], b[np * 2][1], b[np * 2 + 1][0], b[np * 2 + 1][1],
                          vs + swz256(krow, chunk));
            }
#pragma unroll
            for (int mi = 0; mi < 2; mi++)
#pragma unroll
                for (int nj = 0; nj < 8; nj++) mma_f16(o[mi][nj], a[mi], b[nj]);
        }

        // write output chunk (fp16)
#pragma unroll
        for (int mi = 0; mi < 2; mi++) {
            int r0 = blk * 128 + half * 64 + wm + mi * 16 + g;
#pragma unroll
            for (int nj = 0; nj < 8; nj++) {
                int col = c * 128 + wn + nj * 8 + tig * 2;
                *reinterpret_cast<__half2*>(&attn_out[(size_t)r0 * HH + col]) =
                    __floats2half2_rn(o[mi][nj][0], o[mi][nj][1]);
                *reinterpret_cast<__half2*>(&attn_out[(size_t)(r0 + 8) * HH + col]) =
                    __floats2half2_rn(o[mi][nj][2], o[mi][nj][3]);
            }
        }
    }
}

// ---------------------------------------------------------------------------
extern "C" void kernel_launch(void* const* d_in, const int* in_sizes, int n_in,
                              void* d_out, int out_size) {
    const float* x    = (const float*)d_in[0];
    const float* Wqkv = (const float*)d_in[1];
    const float* Wout = (const float*)d_in[2];
    const float* bout = (const float*)d_in[3];
    float* out = (float*)d_out;

    __half *qkvh, *attnh, *xh, *wqkvt, *wouth;
    cudaGetSymbolAddress((void**)&qkvh, g_qkvh);
    cudaGetSymbolAddress((void**)&attnh, g_attnh);
    cudaGetSymbolAddress((void**)&xh, g_xh);
    cudaGetSymbolAddress((void**)&wqkvt, g_wqkvt);
    cudaGetSymbolAddress((void**)&wouth, g_wouth);

    // conversions
    cvt_half_kernel<<<2048, 256>>>(x, xh, (NTOK * EE) / 4);
    transpose_cvt_kernel<<<dim3(QKV_LD / 32, EE / 32), dim3(32, 8)>>>(
        Wqkv, wqkvt, EE, QKV_LD);
    cvt_half_kernel<<<512, 256>>>(Wout, wouth, (HH * HH) / 4);

    // GEMM1: qkvh = xh @ wqkvt^T   [16384, 3072] (fp16 out)
    {
        cudaFuncSetAttribute(hgemm_kernel<true, false>,
                             cudaFuncAttributeMaxDynamicSharedMemorySize, G_SMEM);
        dim3 grid(QKV_LD / 128, NTOK / 128);   // (24, 128)
        hgemm_kernel<true, false><<<grid, 128, G_SMEM>>>(
            xh, wqkvt, nullptr, qkvh, NTOK, QKV_LD, EE);
    }

    // Attention: 256 CTAs (2 per block), 128 threads, occ 2
    {
        cudaFuncSetAttribute(attn_tc_kernel,
                             cudaFuncAttributeMaxDynamicSharedMemorySize, A2_SMEM);
        attn_tc_kernel<<<BB * (SS / 128) * 2, 128, A2_SMEM>>>(qkvh, attnh);
    }

    // GEMM3: out = attnh @ wouth^T + bout   [16384, 1024] (fp32 out)
    {
        cudaFuncSetAttribute(hgemm_kernel<false, true>,
                             cudaFuncAttributeMaxDynamicSharedMemorySize, G_SMEM);
        dim3 grid(HH / 128, NTOK / 128);       // (8, 128)
        hgemm_kernel<false, true><<<grid, 128, G_SMEM>>>(
            attnh, wouth, bout, out, NTOK, HH, HH);
    }
}